// round 8
// baseline (speedup 1.0000x reference)
#include <cuda_runtime.h>
#include <cuda_fp16.h>
#include <cstdint>

// ---------------------------------------------------------------------------
// Problem constants
// ---------------------------------------------------------------------------
#define B_DIM 32
#define W_DIM 16
#define N_DIM 256

// Wgh[w][s][m][n] fp16 weights (8.4 MB), L2-resident.
__device__ __half g_Wgh[W_DIM * 4 * N_DIM * N_DIM];

// ---------------------------------------------------------------------------
// Kernel 1: Wgh[w][s][m][n] = fp16(bias_table[rel_index[m][n], s*16+w])
// ---------------------------------------------------------------------------
__global__ __launch_bounds__(256) void build_weights(
    const float* __restrict__ bias_table, const int* __restrict__ rel_index)
{
    __shared__ float tile[128][65];
    __shared__ int rels[128];
    const int m  = blockIdx.x;
    const int n0 = blockIdx.y * 128;
    const int tid = threadIdx.x;

    if (tid < 128) rels[tid] = rel_index[m * N_DIM + n0 + tid];
    __syncthreads();

#pragma unroll
    for (int i = 0; i < 32; i++) {
        int u = tid + i * 256;
        int n = u >> 6, c = u & 63;
        tile[n][c] = bias_table[rels[n] * 64 + c];
    }
    __syncthreads();

    __half2* g2 = reinterpret_cast<__half2*>(g_Wgh);
#pragma unroll
    for (int i = 0; i < 16; i++) {
        int u = tid + i * 256;
        int c = u >> 6, n2 = u & 63;
        int wq = c & 15, s = c >> 4;
        g2[(((wq * 4 + s) * N_DIM + m) << 7) + (n0 >> 1) + n2] =
            __floats2half2_rn(tile[2 * n2][c], tile[2 * n2 + 1][c]);
    }
}

// ---------------------------------------------------------------------------
// MMA / ldmatrix helpers
// ---------------------------------------------------------------------------
__device__ __forceinline__ void ldsm_x4(uint32_t* r, uint32_t addr) {
    asm volatile("ldmatrix.sync.aligned.m8n8.x4.shared.b16 {%0,%1,%2,%3}, [%4];"
        : "=r"(r[0]), "=r"(r[1]), "=r"(r[2]), "=r"(r[3]) : "r"(addr));
}
__device__ __forceinline__ void ldsm_x4_t(uint32_t* r, uint32_t addr) {
    asm volatile("ldmatrix.sync.aligned.m8n8.x4.trans.shared.b16 {%0,%1,%2,%3}, [%4];"
        : "=r"(r[0]), "=r"(r[1]), "=r"(r[2]), "=r"(r[3]) : "r"(addr));
}
__device__ __forceinline__ void hmma(float* d, const uint32_t* a, uint32_t b0, uint32_t b1) {
    asm volatile(
        "mma.sync.aligned.m16n8k16.row.col.f32.f16.f16.f32 "
        "{%0,%1,%2,%3},{%4,%5,%6,%7},{%8,%9},{%0,%1,%2,%3};"
        : "+f"(d[0]), "+f"(d[1]), "+f"(d[2]), "+f"(d[3])
        : "r"(a[0]), "r"(a[1]), "r"(a[2]), "r"(a[3]), "r"(b0), "r"(b1));
}
__device__ __forceinline__ uint32_t pack_h2(float lo, float hi) {
    __half2 h = __floats2half2_rn(lo, hi);
    return *reinterpret_cast<uint32_t*>(&h);
}
__device__ __forceinline__ uint32_t smem_u32(const void* p) {
    uint32_t a;
    asm("{ .reg .u64 t; cvta.to.shared.u64 t, %1; cvt.u32.u64 %0, t; }"
        : "=r"(a) : "l"(p));
    return a;
}

// ---------------------------------------------------------------------------
// Main kernel: CTA = bx -> (mh = bx&1, w = (bx>>1)&15, b = bx>>5).
// OUT tile M=128 x D=256. 512 thr.
// X: resident smem [s][256k][64v] fp16 (rows 128B, swizzle c ^= k&7), filled
//    chunk-by-chunk pipelined with compute (chunk ch+1 filled during ch).
// A: K chunks of 32, 3-stage cp.async [s][128m][32k] fp16
//    (rows 64B, swizzle q ^= (m>>1)&3) -- 3 x 32 KB.
// ---------------------------------------------------------------------------
#define AS_PLANE 8192
#define A_STAGE  32768
#define X_BASE   (3 * A_STAGE)               // 98304
#define XS_PLANE 32768
#define OUT_PITCH 260
#define SMEM_DYN (X_BASE + 4 * XS_PLANE)     // 229376

__global__ __launch_bounds__(512, 1) void pos_map_mm(
    const float* __restrict__ x, const float* __restrict__ token_bias,
    float* __restrict__ out)
{
    extern __shared__ __align__(16) char smem[];
    const int bx = blockIdx.x;
    const int m0 = (bx & 1) * 128, w = (bx >> 1) & 15, b = bx >> 5;
    const int tid = threadIdx.x, lane = tid & 31, warp = tid >> 5;
    const int wm = warp & 3;    // m-group: 32 rows
    const int wc = warp >> 2;   // s-plane
    const uint32_t sbase = smem_u32(smem);

    const __half* WgBase = g_Wgh + (size_t)(w * 4) * 65536 + (size_t)m0 * 256;
    const float4* xb4 = (const float4*)x + (size_t)(b * 16 + w) * (256 * 64);

    float acc[2][8][4];
#pragma unroll
    for (int mt = 0; mt < 2; mt++)
#pragma unroll
        for (int nt = 0; nt < 8; nt++)
#pragma unroll
            for (int j = 0; j < 4; j++) acc[mt][nt][j] = 0.f;

    const int grp  = lane >> 3;
    const int row8 = (grp & 1) * 8 + (lane & 7);
    const int qsel = grp >> 1;

    uint32_t xh[2][4];   // X data for the NEXT chunk (2 units x 4 s-planes)

    auto issue_A = [&](int st, int ch) {
        const int n0c = ch * 32;
#pragma unroll
        for (int i = 0; i < 4; i++) {
            int u = tid + i * 512;                 // 2048 x 16B units
            int s = u >> 9, m = (u >> 2) & 127, q = u & 3;
            const __half* src = WgBase + s * 65536 + m * 256 + n0c + q * 8;
            uint32_t dst = sbase + st * A_STAGE + s * AS_PLANE + m * 64
                         + ((q ^ ((m >> 1) & 3)) << 4);
            asm volatile("cp.async.cg.shared.global [%0], [%1], 16;"
                         :: "r"(dst), "l"(src));
        }
        asm volatile("cp.async.commit_group;");
    };
    auto load_X = [&](int ch) {
        const int n0c = ch * 32;
#pragma unroll
        for (int it = 0; it < 2; it++) {
            int u = tid + it * 512;                // 1024 (k, vpair) units
            int vp = u & 31, k = u >> 5;
            float4 f0 = xb4[(n0c + k) * 64 + 2 * vp];
            float4 f1 = xb4[(n0c + k) * 64 + 2 * vp + 1];
            const float* p0 = reinterpret_cast<const float*>(&f0);
            const float* p1 = reinterpret_cast<const float*>(&f1);
#pragma unroll
            for (int s = 0; s < 4; s++) xh[it][s] = pack_h2(p0[s], p1[s]);
        }
    };
    auto store_X = [&](int ch) {
#pragma unroll
        for (int it = 0; it < 2; it++) {
            int u = tid + it * 512;
            int vp = u & 31, k = ch * 32 + (u >> 5);
            uint32_t off = X_BASE + (uint32_t)k * 128
                         + (((vp >> 2) ^ (k & 7)) << 4) + ((vp & 3) << 2);
#pragma unroll
            for (int s = 0; s < 4; s++)
                *(uint32_t*)(smem + off + s * XS_PLANE) = xh[it][s];
        }
    };

    // ---- prologue: A chunks 0,1 in flight; X chunk 0 filled; chunk 1 in regs
    issue_A(0, 0);
    issue_A(1, 1);
    load_X(0);
    store_X(0);
    load_X(1);
    asm volatile("cp.async.wait_group 1;");
    __syncthreads();

    // ---- main loop: 8 chunks of 32 k ----
    for (int ch = 0; ch < 8; ch++) {
        const int st = ch % 3;
        if (ch < 6) issue_A((ch + 2) % 3, ch + 2);
        if (ch < 7) store_X(ch + 1);      // xh holds chunk ch+1
        if (ch < 6) load_X(ch + 2);       // refill xh (after store consumed it)

        const uint32_t sA = sbase + st * A_STAGE + wc * AS_PLANE;
        const uint32_t sX = sbase + X_BASE + wc * XS_PLANE;
#pragma unroll
        for (int ks = 0; ks < 2; ks++) {
            uint32_t a[2][4];
#pragma unroll
            for (int mt = 0; mt < 2; mt++) {
                int m = wm * 32 + mt * 16 + row8;
                int q = ks * 2 + qsel;
                ldsm_x4(a[mt], sA + m * 64 + ((q ^ ((m >> 1) & 3)) << 4));
            }
            uint32_t bq[4][4];
#pragma unroll
            for (int ng = 0; ng < 4; ng++) {
                int k = ch * 32 + ks * 16 + row8;
                int c = ng * 2 + qsel;
                ldsm_x4_t(bq[ng], sX + k * 128 + ((c ^ (k & 7)) << 4));
            }
#pragma unroll
            for (int mt = 0; mt < 2; mt++)
#pragma unroll
                for (int nt = 0; nt < 8; nt++)
                    hmma(acc[mt][nt], a[mt],
                         bq[nt >> 1][(nt & 1) * 2], bq[nt >> 1][(nt & 1) * 2 + 1]);
        }

        if (ch < 6)      asm volatile("cp.async.wait_group 1;");
        else if (ch == 6) asm volatile("cp.async.wait_group 0;");
        __syncthreads();
    }

    // ---- epilogue: bias add, smem stage (reuses A/X region), f4 store ----
    float* so = (float*)smem;   // [128][OUT_PITCH] = 133120 B < SMEM_DYN
#pragma unroll
    for (int mt = 0; mt < 2; mt++)
#pragma unroll
        for (int j = 0; j < 2; j++) {
            int m = wm * 32 + mt * 16 + (lane >> 2) + j * 8;
            float tb = token_bias[(w * 4 + wc) * 256 + m0 + m];
            float* dr = so + m * OUT_PITCH + wc;
#pragma unroll
            for (int nt = 0; nt < 8; nt++) {
                int v = nt * 8 + ((lane & 3) << 1);
                dr[v * 4]       = acc[mt][nt][j * 2 + 0] + tb;
                dr[(v + 1) * 4] = acc[mt][nt][j * 2 + 1] + tb;
            }
        }
    __syncthreads();

    float4* ob = (float4*)(out + (size_t)((b * 16 + w) * 256 + m0) * 256);
#pragma unroll
    for (int i = 0; i < 16; i++) {
        int u = tid + i * 512;
        int row = u >> 6, c = u & 63;
        ob[row * 64 + c] = *(float4*)(so + row * OUT_PITCH + c * 4);
    }
}

// ---------------------------------------------------------------------------
// Launch: inputs in metadata order: x, bias_table, token_bias, rel_index
// ---------------------------------------------------------------------------
extern "C" void kernel_launch(void* const* d_in, const int* in_sizes, int n_in,
                              void* d_out, int out_size)
{
    const float* x          = (const float*)d_in[0];
    const float* bias_table = (const float*)d_in[1];
    const float* token_bias = (const float*)d_in[2];
    const int*   rel_index  = (const int*)d_in[3];
    float* out = (float*)d_out;
    (void)in_sizes; (void)n_in; (void)out_size;

    cudaFuncSetAttribute(pos_map_mm,
                         cudaFuncAttributeMaxDynamicSharedMemorySize, SMEM_DYN);

    build_weights<<<dim3(256, 2), 256>>>(bias_table, rel_index);
    pos_map_mm<<<1024, 512, SMEM_DYN>>>(x, token_bias, out);
}

// round 9
// speedup vs baseline: 1.0657x; 1.0657x over previous
#include <cuda_runtime.h>
#include <cuda_fp16.h>
#include <cstdint>

// ---------------------------------------------------------------------------
// Problem constants
// ---------------------------------------------------------------------------
#define B_DIM 32
#define W_DIM 16
#define N_DIM 256

// Wgh[w][s][m][n] fp16 weights (8.4 MB), L2-resident.
__device__ __half g_Wgh[W_DIM * 4 * N_DIM * N_DIM];

// ---------------------------------------------------------------------------
// Kernel 1: Wgh[w][s][m][n] = fp16(bias_table[rel_index[m][n], s*16+w])
// ---------------------------------------------------------------------------
__global__ __launch_bounds__(256) void build_weights(
    const float* __restrict__ bias_table, const int* __restrict__ rel_index)
{
    __shared__ float tile[128][65];
    __shared__ int rels[128];
    const int m  = blockIdx.x;
    const int n0 = blockIdx.y * 128;
    const int tid = threadIdx.x;

    if (tid < 128) rels[tid] = rel_index[m * N_DIM + n0 + tid];
    __syncthreads();

#pragma unroll
    for (int i = 0; i < 32; i++) {
        int u = tid + i * 256;
        int n = u >> 6, c = u & 63;
        tile[n][c] = bias_table[rels[n] * 64 + c];
    }
    __syncthreads();

    __half2* g2 = reinterpret_cast<__half2*>(g_Wgh);
#pragma unroll
    for (int i = 0; i < 16; i++) {
        int u = tid + i * 256;
        int c = u >> 6, n2 = u & 63;
        int wq = c & 15, s = c >> 4;
        g2[(((wq * 4 + s) * N_DIM + m) << 7) + (n0 >> 1) + n2] =
            __floats2half2_rn(tile[2 * n2][c], tile[2 * n2 + 1][c]);
    }
}

// ---------------------------------------------------------------------------
// MMA / ldmatrix helpers
// ---------------------------------------------------------------------------
__device__ __forceinline__ void ldsm_x4(uint32_t* r, uint32_t addr) {
    asm volatile("ldmatrix.sync.aligned.m8n8.x4.shared.b16 {%0,%1,%2,%3}, [%4];"
        : "=r"(r[0]), "=r"(r[1]), "=r"(r[2]), "=r"(r[3]) : "r"(addr));
}
__device__ __forceinline__ void ldsm_x4_t(uint32_t* r, uint32_t addr) {
    asm volatile("ldmatrix.sync.aligned.m8n8.x4.trans.shared.b16 {%0,%1,%2,%3}, [%4];"
        : "=r"(r[0]), "=r"(r[1]), "=r"(r[2]), "=r"(r[3]) : "r"(addr));
}
__device__ __forceinline__ void hmma(float* d, const uint32_t* a, uint32_t b0, uint32_t b1) {
    asm volatile(
        "mma.sync.aligned.m16n8k16.row.col.f32.f16.f16.f32 "
        "{%0,%1,%2,%3},{%4,%5,%6,%7},{%8,%9},{%0,%1,%2,%3};"
        : "+f"(d[0]), "+f"(d[1]), "+f"(d[2]), "+f"(d[3])
        : "r"(a[0]), "r"(a[1]), "r"(a[2]), "r"(a[3]), "r"(b0), "r"(b1));
}
__device__ __forceinline__ uint32_t pack_h2(float lo, float hi) {
    __half2 h = __floats2half2_rn(lo, hi);
    return *reinterpret_cast<uint32_t*>(&h);
}
__device__ __forceinline__ uint32_t smem_u32(const void* p) {
    uint32_t a;
    asm("{ .reg .u64 t; cvta.to.shared.u64 t, %1; cvt.u32.u64 %0, t; }"
        : "=r"(a) : "l"(p));
    return a;
}

// ---------------------------------------------------------------------------
// Main kernel: CTA = bx -> (mh = bx&1, w = (bx>>1)&15, b = bx>>5).
// OUT tile M=128 x D=256. 256 threads / 8 warps; warp tile 64m x 64v
// (warp = wm(2 m-halves) x wc(4 s-planes)), acc[4][8][4] = 128 regs.
// X: resident smem [s][256k][64v] fp16 (rows 128B, swizzle c ^= k&7),
//    converted once in the prologue (overlapped with A chunk 0 cp.async).
// A: K chunks of 32, double-buffered cp.async [s][128m][32k] fp16
//    (rows 64B, swizzle q ^= (m>>1)&3) -- 2 x 32 KB.
// ---------------------------------------------------------------------------
#define AS_PLANE 8192
#define A_STAGE  32768
#define X_BASE   (2 * A_STAGE)               // 65536
#define XS_PLANE 32768
#define OUT_PITCH 260
#define SMEM_DYN (X_BASE + 4 * XS_PLANE)     // 196608

__global__ __launch_bounds__(256, 1) void pos_map_mm(
    const float* __restrict__ x, const float* __restrict__ token_bias,
    float* __restrict__ out)
{
    extern __shared__ __align__(16) char smem[];
    const int bx = blockIdx.x;
    const int m0 = (bx & 1) * 128, w = (bx >> 1) & 15, b = bx >> 5;
    const int tid = threadIdx.x, lane = tid & 31, warp = tid >> 5;
    const int wm = warp >> 2;   // m-half of tile: 64 rows
    const int wc = warp & 3;    // s-plane
    const uint32_t sbase = smem_u32(smem);

    const __half* WgBase = g_Wgh + (size_t)(w * 4) * 65536 + (size_t)m0 * 256;
    const float4* xb4 = (const float4*)x + (size_t)(b * 16 + w) * (256 * 64);

    float acc[4][8][4];
#pragma unroll
    for (int mt = 0; mt < 4; mt++)
#pragma unroll
        for (int nt = 0; nt < 8; nt++)
#pragma unroll
            for (int j = 0; j < 4; j++) acc[mt][nt][j] = 0.f;

    const int grp  = lane >> 3;
    const int row8 = (grp & 1) * 8 + (lane & 7);
    const int qsel = grp >> 1;

    auto issue_A = [&](int st, int ch) {
        const int n0c = ch * 32;
#pragma unroll
        for (int i = 0; i < 8; i++) {
            int u = tid + i * 256;                 // 2048 x 16B units
            int s = u >> 9, m = (u >> 2) & 127, q = u & 3;
            const __half* src = WgBase + s * 65536 + m * 256 + n0c + q * 8;
            uint32_t dst = sbase + st * A_STAGE + s * AS_PLANE + m * 64
                         + ((q ^ ((m >> 1) & 3)) << 4);
            asm volatile("cp.async.cg.shared.global [%0], [%1], 16;"
                         :: "r"(dst), "l"(src));
        }
        asm volatile("cp.async.commit_group;");
    };

    // ---- prologue: A chunk 0 in flight; fill resident X ----
    issue_A(0, 0);

#pragma unroll
    for (int i = 0; i < 32; i++) {
        int u = tid + i * 256;                 // 8192 units: 256k x 32vp
        int k = u >> 5, vp = u & 31;
        float4 f0 = xb4[k * 64 + 2 * vp];
        float4 f1 = xb4[k * 64 + 2 * vp + 1];
        const float* p0 = reinterpret_cast<const float*>(&f0);
        const float* p1 = reinterpret_cast<const float*>(&f1);
        uint32_t off = X_BASE + (uint32_t)k * 128
                     + (((vp >> 2) ^ (k & 7)) << 4) + ((vp & 3) << 2);
#pragma unroll
        for (int s = 0; s < 4; s++)
            *(uint32_t*)(smem + off + s * XS_PLANE) = pack_h2(p0[s], p1[s]);
    }

    asm volatile("cp.async.wait_group 0;");
    __syncthreads();

    // ---- main loop: 8 A-chunks of 32 k (fully unrolled) ----
#pragma unroll
    for (int ch = 0; ch < 8; ch++) {
        const int st = ch & 1;
        if (ch < 7) issue_A((ch + 1) & 1, ch + 1);

        const uint32_t sA = sbase + st * A_STAGE + wc * AS_PLANE;
        const uint32_t sX = sbase + X_BASE + wc * XS_PLANE;
#pragma unroll
        for (int ks = 0; ks < 2; ks++) {
            uint32_t a[4][4];
#pragma unroll
            for (int mt = 0; mt < 4; mt++) {
                int m = wm * 64 + mt * 16 + row8;
                int q = ks * 2 + qsel;
                ldsm_x4(a[mt], sA + m * 64 + ((q ^ ((m >> 1) & 3)) << 4));
            }
            uint32_t bq[4][4];
#pragma unroll
            for (int ng = 0; ng < 4; ng++) {
                int k = ch * 32 + ks * 16 + row8;
                int c = ng * 2 + qsel;
                ldsm_x4_t(bq[ng], sX + k * 128 + ((c ^ (k & 7)) << 4));
            }
#pragma unroll
            for (int mt = 0; mt < 4; mt++)
#pragma unroll
                for (int nt = 0; nt < 8; nt++)
                    hmma(acc[mt][nt], a[mt],
                         bq[nt >> 1][(nt & 1) * 2], bq[nt >> 1][(nt & 1) * 2 + 1]);
        }

        asm volatile("cp.async.wait_group 0;");
        __syncthreads();
    }

    // ---- epilogue: bias add, smem stage (reuses A/X region), f4 store ----
    float* so = (float*)smem;   // [128][OUT_PITCH] = 133120 B < SMEM_DYN
#pragma unroll
    for (int mt = 0; mt < 4; mt++)
#pragma unroll
        for (int j = 0; j < 2; j++) {
            int m = wm * 64 + mt * 16 + (lane >> 2) + j * 8;
            float tb = token_bias[(w * 4 + wc) * 256 + m0 + m];
            float* dr = so + m * OUT_PITCH + wc;
#pragma unroll
            for (int nt = 0; nt < 8; nt++) {
                int v = nt * 8 + ((lane & 3) << 1);
                dr[v * 4]       = acc[mt][nt][j * 2 + 0] + tb;
                dr[(v + 1) * 4] = acc[mt][nt][j * 2 + 1] + tb;
            }
        }
    __syncthreads();

    float4* ob = (float4*)(out + (size_t)((b * 16 + w) * 256 + m0) * 256);
#pragma unroll
    for (int i = 0; i < 16; i++) {
        int u = tid + i * 256;
        int row = u >> 6, c = u & 63;
        ob[row * 64 + c] = *(float4*)(so + row * OUT_PITCH + c * 4);
        u = tid + (i + 16) * 256;
        row = u >> 6; c = u & 63;
        ob[row * 64 + c] = *(float4*)(so + row * OUT_PITCH + c * 4);
    }
}

// ---------------------------------------------------------------------------
// Launch: inputs in metadata order: x, bias_table, token_bias, rel_index
// ---------------------------------------------------------------------------
extern "C" void kernel_launch(void* const* d_in, const int* in_sizes, int n_in,
                              void* d_out, int out_size)
{
    const float* x          = (const float*)d_in[0];
    const float* bias_table = (const float*)d_in[1];
    const float* token_bias = (const float*)d_in[2];
    const int*   rel_index  = (const int*)d_in[3];
    float* out = (float*)d_out;
    (void)in_sizes; (void)n_in; (void)out_size;

    cudaFuncSetAttribute(pos_map_mm,
                         cudaFuncAttributeMaxDynamicSharedMemorySize, SMEM_DYN);

    build_weights<<<dim3(256, 2), 256>>>(bias_table, rel_index);
    pos_map_mm<<<1024, 256, SMEM_DYN>>>(x, token_bias, out);
}